// round 17
// baseline (speedup 1.0000x reference)
#include <cuda_runtime.h>
#include <cuda_fp16.h>
#include <cstdint>

#define D_      128
#define NVARS   50000
#define V2_     100000
#define NCL     200000
#define NTOTAL  300000
#define NROUNDS 16
#define EDG     800000

// ---------------- persistent scratch ---------------------------------------
__device__ float g_h[(size_t)NTOTAL * D_];
__device__ float g_c[(size_t)NTOTAL * D_];
__device__ uint32_t g_t0[(size_t)NCL * 64];      // fp16 MLP output (half2 packed)

// fp16 mirrors (u32 = packed half2, 64 u32 per 128-float row)
__device__ uint32_t g_chh[(size_t)NCL * 64];     // clause h (in-place safe)
__device__ uint32_t g_lhA[(size_t)V2_ * 64];     // literal h ping
__device__ uint32_t g_lhB[(size_t)V2_ * 64];     // literal h pong
__device__ uint32_t g_mm[(size_t)NCL * 64];      // messages
// weights (u32 = packed half2); gate matrices stored ROW-PERMUTED
#define WO_LMSG  0
#define WO_CMSG  24576
#define WO_CWIH  49152
#define WO_CWHH  81920
#define WO_LWIH  114688
#define WO_LWHH  180224
#define W_TOTAL  212992
__device__ uint32_t g_wh[W_TOTAL];
__device__ float g_pbC[512];
__device__ float g_pbL[512];

// CSR edge structures
__device__ int g_cntC[NCL + 1];
__device__ int g_cntL[V2_ + 1];
__device__ int g_curC[NCL];
__device__ int g_curL[V2_];
__device__ int g_srcC[EDG];
__device__ int g_srcL[EDG];

// ---------------- helpers ---------------------------------------------------
__device__ __forceinline__ uint32_t cvt2h(float x, float y) {
    __half2 hp = __floats2half2_rn(x, y);
    return *(uint32_t*)&hp;
}

__device__ __forceinline__ void mma_f16(float* d, const uint32_t* a, uint32_t b0, uint32_t b1) {
    asm volatile(
        "mma.sync.aligned.m16n8k16.row.col.f32.f16.f16.f32 "
        "{%0,%1,%2,%3}, {%4,%5,%6,%7}, {%8,%9}, {%0,%1,%2,%3};\n"
        : "+f"(d[0]), "+f"(d[1]), "+f"(d[2]), "+f"(d[3])
        : "r"(a[0]), "r"(a[1]), "r"(a[2]), "r"(a[3]), "r"(b0), "r"(b1));
}

__device__ __forceinline__ uint32_t smem_u32(const void* p) {
    uint32_t a;
    asm("{ .reg .u64 t; cvta.to.shared.u64 t, %1; cvt.u32.u64 %0, t; }" : "=r"(a) : "l"(p));
    return a;
}

__device__ __forceinline__ void cp16(uint32_t saddr, const void* g, bool pred) {
    int sz = pred ? 16 : 0;
    asm volatile("cp.async.cg.shared.global [%0], [%1], 16, %2;"
                 :: "r"(saddr), "l"(g), "r"(sz));
}
#define CP_COMMIT() asm volatile("cp.async.commit_group;" ::: "memory")

__device__ __forceinline__ float sigf(float x) {
    return __fdividef(1.f, 1.f + __expf(-x));
}
__device__ __forceinline__ float tanhfast(float x) {
    return __fdividef(2.f, 1.f + __expf(-2.f * x)) - 1.f;
}

#define ASTR 36
#define SUB  4608
#define SMEM_MLP ((size_t)(6 * SUB) * 4)   // 110592 B
#define SMEM_G2  ((size_t)(6 * SUB) * 4)
#define SMEM_G3  ((size_t)(8 * SUB) * 4)   // 147456 B: A0,A1,A2 (2 SUB each) + W (2 SUB)

// fill one K=64 half-tile from a 64-u32/row array
__device__ __forceinline__ void fill_half(uint32_t sb, uint32_t dst_u32,
                                          const uint32_t* __restrict__ gh,
                                          int rowbase, int kh, int M, int tid,
                                          int nflip) {
#pragma unroll
    for (int i = 0; i < 2; ++i) {
        int f = i * 512 + tid;
        int r = f >> 3, cch = f & 7;
        int gr = rowbase + r;
        bool p = gr < M;
        int src = p ? gr : 0;
        if (nflip) src = (src < NVARS) ? src + NVARS : src - NVARS;
        size_t go = (size_t)src * 64 + kh * 32 + cch * 4;
        uint32_t so = sb + (dst_u32 + (uint32_t)(r * ASTR + cch * 4)) * 4;
        cp16(so, gh + go, p);
    }
}

// fill one K=64 half-tile of weights with explicit ld/koffset (u32 units)
__device__ __forceinline__ void fill_w(uint32_t sb, uint32_t dst_u32,
                                       const uint32_t* __restrict__ gh,
                                       int rowbase, int kh, int ldb, int bko, int tid) {
#pragma unroll
    for (int i = 0; i < 2; ++i) {
        int f = i * 512 + tid;
        int r = f >> 3, cch = f & 7;
        size_t go = (size_t)(rowbase + r) * ldb + bko + kh * 32 + cch * 4;
        uint32_t so = sb + (dst_u32 + (uint32_t)(r * ASTR + cch * 4)) * 4;
        cp16(so, gh + go, true);
    }
}

__device__ __forceinline__ void compute_half(const uint32_t* __restrict__ SA,
                                             const uint32_t* __restrict__ SW,
                                             float acc[2][4][4],
                                             int wm, int wn, int g, int t) {
#pragma unroll
    for (int ks = 0; ks < 4; ++ks) {
        const int c0 = ks * 8 + t;
        uint32_t ah[2][4];
#pragma unroll
        for (int mf = 0; mf < 2; ++mf) {
            const int r = wm + mf * 16 + g;
            const uint32_t* p = SA + r * ASTR + c0;
            ah[mf][0] = p[0]; ah[mf][1] = p[8 * ASTR];
            ah[mf][2] = p[4]; ah[mf][3] = p[8 * ASTR + 4];
        }
#pragma unroll
        for (int nf = 0; nf < 4; ++nf) {
            const int nr = wn + nf * 8 + g;
            const uint32_t* pb = SW + nr * ASTR + c0;
            uint32_t b0 = pb[0], b1 = pb[4];
#pragma unroll
            for (int mf = 0; mf < 2; ++mf)
                mma_f16(acc[mf][nf], ah[mf], b0, b1);
        }
    }
}

// in-register LSTM epilogue (gate-interleaved permuted weights)
__device__ __forceinline__ void lstm_epi(
    float acc[2][4][4], const float* __restrict__ pb, int ntcol,
    int wm, int wn, int g, int t, int brow, int M,
    float* __restrict__ cbuf, float* __restrict__ hout,
    uint32_t* __restrict__ hhout) {
    float bg[4][2];
#pragma unroll
    for (int nf = 0; nf < 4; ++nf) {
        int col = ntcol + wn + nf * 8 + 2 * t;
        bg[nf][0] = pb[col]; bg[nf][1] = pb[col + 1];
    }
    const int f0 = (ntcol >> 2) + (wn >> 2) + 2 * t;
#pragma unroll
    for (int mf = 0; mf < 2; ++mf) {
#pragma unroll
        for (int half = 0; half < 2; ++half) {
            const int row = brow + wm + mf * 16 + g + half * 8;
            if (row < M) {
                const int k0 = half * 2;
                float hres[2];
#pragma unroll
                for (int p = 0; p < 2; ++p) {
                    float iv = acc[mf][0][k0 + p] + bg[0][p];
                    float fv = acc[mf][1][k0 + p] + bg[1][p];
                    float gv = acc[mf][2][k0 + p] + bg[2][p];
                    float ov = acc[mf][3][k0 + p] + bg[3][p];
                    float cc = cbuf[(size_t)row * D_ + f0 + p];
                    float c2 = sigf(fv) * cc + sigf(iv) * tanhfast(gv);
                    float hv = sigf(ov) * tanhfast(c2);
                    cbuf[(size_t)row * D_ + f0 + p] = c2;
                    hout[(size_t)row * D_ + f0 + p] = hv;
                    hres[p] = hv;
                }
                hhout[(size_t)row * 64 + (f0 >> 1)] = cvt2h(hres[0], hres[1]);
            }
        }
    }
}

// ---------------- fused 3-layer MLP (fp16 out) -------------------------------
__global__ __launch_bounds__(512, 2) void mlp3_kernel(
    const uint32_t* __restrict__ Ah,
    const uint32_t* __restrict__ Wh,
    const float* __restrict__ bias, uint32_t* __restrict__ Cout, int M) {
    extern __shared__ uint32_t sm[];
    const uint32_t sb = smem_u32(sm);
    const int tid  = threadIdx.x;
    const int wid  = tid >> 5;
    const int lane = tid & 31;
    const int g    = lane >> 2;
    const int t    = lane & 3;
    const int wm   = (wid >> 2) * 32;
    const int wn   = (wid & 3) * 32;
    const int brow = blockIdx.x << 7;

    fill_half(sb, 0,   Ah, brow, 0, M, tid, 0);
    fill_half(sb, SUB, Ah, brow, 1, M, tid, 0);
    CP_COMMIT();
    fill_half(sb, 2 * SUB, Wh, 0, 0, 128, tid, 0);
    fill_half(sb, 3 * SUB, Wh, 0, 1, 128, tid, 0);
    CP_COMMIT();

#pragma unroll
    for (int layer = 0; layer < 3; ++layer) {
        if (layer < 2) {
            const uint32_t wd = 2 * SUB + 2 * SUB * ((layer + 1) & 1);
            fill_half(sb, wd,       Wh + (layer + 1) * 8192, 0, 0, 128, tid, 0);
            fill_half(sb, wd + SUB, Wh + (layer + 1) * 8192, 0, 1, 128, tid, 0);
            CP_COMMIT();
            asm volatile("cp.async.wait_group 1;" ::: "memory");
        } else {
            asm volatile("cp.async.wait_group 0;" ::: "memory");
        }
        __syncthreads();

        const uint32_t* W = sm + 2 * SUB + 2 * SUB * (layer & 1);
        float acc[2][4][4];
#pragma unroll
        for (int mf = 0; mf < 2; ++mf)
#pragma unroll
            for (int nf = 0; nf < 4; ++nf)
#pragma unroll
                for (int k = 0; k < 4; ++k) acc[mf][nf][k] = 0.f;

        compute_half(sm,       W,       acc, wm, wn, g, t);
        compute_half(sm + SUB, W + SUB, acc, wm, wn, g, t);
        __syncthreads();

        const float* bl = bias + layer * 128;
        if (layer < 2) {
#pragma unroll
            for (int nf = 0; nf < 4; ++nf) {
                const int col = wn + nf * 8 + 2 * t;
                float b0v = bl[col], b1v = bl[col + 1];
                const int c32 = col >> 1;
                const uint32_t hbase = (c32 >> 5) * SUB;
                const int off = c32 & 31;
#pragma unroll
                for (int mf = 0; mf < 2; ++mf) {
                    const int r = wm + mf * 16 + g;
                    float x0 = fmaxf(acc[mf][nf][0] + b0v, 0.f);
                    float x1 = fmaxf(acc[mf][nf][1] + b1v, 0.f);
                    float x2 = fmaxf(acc[mf][nf][2] + b0v, 0.f);
                    float x3 = fmaxf(acc[mf][nf][3] + b1v, 0.f);
                    sm[hbase + r * ASTR + off]       = cvt2h(x0, x1);
                    sm[hbase + (r + 8) * ASTR + off] = cvt2h(x2, x3);
                }
            }
            __syncthreads();
        } else {
            // final: fp16 half2 out
#pragma unroll
            for (int nf = 0; nf < 4; ++nf) {
                const int col = wn + nf * 8 + 2 * t;
                float b0v = bl[col], b1v = bl[col + 1];
                const int c32 = col >> 1;
#pragma unroll
                for (int mf = 0; mf < 2; ++mf) {
                    const int row = brow + wm + mf * 16 + g;
                    if (row < M)
                        Cout[(size_t)row * 64 + c32] =
                            cvt2h(acc[mf][nf][0] + b0v, acc[mf][nf][1] + b1v);
                    if (row + 8 < M)
                        Cout[(size_t)(row + 8) * 64 + c32] =
                            cvt2h(acc[mf][nf][2] + b0v, acc[mf][nf][3] + b1v);
                }
            }
        }
    }
}

// ---------------- fused 2-term gates GEMM + in-register LSTM -----------------
__global__ __launch_bounds__(512, 2) void gates2_kernel(
    const uint32_t* __restrict__ A0h, const uint32_t* __restrict__ A1h,
    const uint32_t* __restrict__ Wihh, const uint32_t* __restrict__ Whhh,
    const float* __restrict__ pb,
    float* __restrict__ cbuf, float* __restrict__ hout,
    uint32_t* __restrict__ hhout, int M) {
    extern __shared__ uint32_t sm[];
    const uint32_t sb = smem_u32(sm);
    const int tid  = threadIdx.x;
    const int wid  = tid >> 5;
    const int lane = tid & 31;
    const int g    = lane >> 2;
    const int t    = lane & 3;
    const int wm   = (wid >> 2) * 32;
    const int wn   = (wid & 3) * 32;
    const int brow = blockIdx.x << 7;

    fill_half(sb, 0,       A0h, brow, 0, M, tid, 0);
    fill_half(sb, SUB,     A0h, brow, 1, M, tid, 0);
    fill_half(sb, 2 * SUB, A1h, brow, 0, M, tid, 0);
    fill_half(sb, 3 * SUB, A1h, brow, 1, M, tid, 0);
    CP_COMMIT();

    const uint32_t WB = 4 * SUB;
    for (int nt = 0; nt < 4; ++nt) {
        float acc[2][4][4];
#pragma unroll
        for (int mf = 0; mf < 2; ++mf)
#pragma unroll
            for (int nf = 0; nf < 4; ++nf)
#pragma unroll
                for (int k = 0; k < 4; ++k) acc[mf][nf][k] = 0.f;

#pragma unroll
        for (int term = 0; term < 2; ++term) {
            const uint32_t* wh = term ? Whhh : Wihh;
            fill_w(sb, WB,       wh, nt * 128, 0, 64, 0, tid);
            CP_COMMIT();
            fill_w(sb, WB + SUB, wh, nt * 128, 1, 64, 0, tid);
            CP_COMMIT();
            asm volatile("cp.async.wait_group 1;" ::: "memory");
            __syncthreads();
            compute_half(sm + term * 2 * SUB, sm + WB, acc, wm, wn, g, t);
            asm volatile("cp.async.wait_group 0;" ::: "memory");
            __syncthreads();
            compute_half(sm + term * 2 * SUB + SUB, sm + WB + SUB, acc, wm, wn, g, t);
            __syncthreads();
        }
        lstm_epi(acc, pb, nt * 128, wm, wn, g, t, brow, M, cbuf, hout, hhout);
    }
}

// ---------------- fused 3-term gates GEMM + LSTM (A resident, nt loop) -------
__global__ __launch_bounds__(512) void gates3_kernel(
    const uint32_t* __restrict__ A0h,   // messages
    const uint32_t* __restrict__ A1h,   // literal h (neg-flipped rows)
    const uint32_t* __restrict__ Wih,   // [512,128] permuted
    const uint32_t* __restrict__ Whh,   // [512,64]  permuted
    const float* __restrict__ pb,
    float* __restrict__ cbuf, float* __restrict__ hout,
    uint32_t* __restrict__ hhout, int M) {
    extern __shared__ uint32_t sm[];
    const uint32_t sb = smem_u32(sm);
    const int tid  = threadIdx.x;
    const int wid  = tid >> 5;
    const int lane = tid & 31;
    const int g    = lane >> 2;
    const int t    = lane & 3;
    const int wm   = (wid >> 2) * 32;
    const int wn   = (wid & 3) * 32;
    const int brow = blockIdx.x << 7;

    // A: term0 = msg, term1 = neg-flipped h, term2 = h
    fill_half(sb, 0,       A0h, brow, 0, M, tid, 0);
    fill_half(sb, SUB,     A0h, brow, 1, M, tid, 0);
    fill_half(sb, 2 * SUB, A1h, brow, 0, M, tid, 1);
    fill_half(sb, 3 * SUB, A1h, brow, 1, M, tid, 1);
    fill_half(sb, 4 * SUB, A1h, brow, 0, M, tid, 0);
    fill_half(sb, 5 * SUB, A1h, brow, 1, M, tid, 0);
    CP_COMMIT();

    const uint32_t WB = 6 * SUB;
    for (int nt = 0; nt < 4; ++nt) {
        float acc[2][4][4];
#pragma unroll
        for (int mf = 0; mf < 2; ++mf)
#pragma unroll
            for (int nf = 0; nf < 4; ++nf)
#pragma unroll
                for (int k = 0; k < 4; ++k) acc[mf][nf][k] = 0.f;

#pragma unroll
        for (int term = 0; term < 3; ++term) {
            const uint32_t* wsrc = (term < 2) ? Wih : Whh;
            const int ldb = (term < 2) ? 128 : 64;
            const int bko = (term == 1) ? 64 : 0;
            fill_w(sb, WB,       wsrc, nt * 128, 0, ldb, bko, tid);
            CP_COMMIT();
            fill_w(sb, WB + SUB, wsrc, nt * 128, 1, ldb, bko, tid);
            CP_COMMIT();
            asm volatile("cp.async.wait_group 1;" ::: "memory");
            __syncthreads();
            compute_half(sm + term * 2 * SUB, sm + WB, acc, wm, wn, g, t);
            asm volatile("cp.async.wait_group 0;" ::: "memory");
            __syncthreads();
            compute_half(sm + term * 2 * SUB + SUB, sm + WB + SUB, acc, wm, wn, g, t);
            __syncthreads();
        }
        lstm_epi(acc, pb, nt * 128, wm, wn, g, t, brow, M, cbuf, hout, hhout);
    }
}

// ---------------- CSR build ---------------------------------------------------
__global__ void zero_int_kernel(int* __restrict__ p, int n) {
    int i = blockIdx.x * 256 + threadIdx.x;
    if (i < n) p[i] = 0;
}

__global__ void hist_kernel(const int* __restrict__ esrc, const int* __restrict__ edst,
                            int* __restrict__ cntC, int* __restrict__ cntL, int E) {
    int e = blockIdx.x * 256 + threadIdx.x;
    if (e >= E) return;
    atomicAdd(&cntC[edst[e]], 1);
    atomicAdd(&cntL[esrc[e]], 1);
}

__global__ __launch_bounds__(1024) void scan_kernel(int* __restrict__ cnt,
                                                    int* __restrict__ cur, int n) {
    __shared__ int ts[1024];
    const int t = threadIdx.x;
    const int chunk = (n + 1023) / 1024;
    const int beg = t * chunk;
    const int end = min(beg + chunk, n);
    int s = 0;
    for (int i = beg; i < end; ++i) s += cnt[i];
    ts[t] = s;
    __syncthreads();
    for (int off = 1; off < 1024; off <<= 1) {
        int v = (t >= off) ? ts[t - off] : 0;
        __syncthreads();
        ts[t] += v;
        __syncthreads();
    }
    int run = (t == 0) ? 0 : ts[t - 1];
    for (int i = beg; i < end; ++i) {
        int cv = cnt[i];
        cnt[i] = run;
        cur[i] = run;
        run += cv;
    }
    if (beg < n && end == n) cnt[n] = run;
}

__global__ void place_kernel(const int* __restrict__ esrc, const int* __restrict__ edst,
                             int* __restrict__ curC, int* __restrict__ curL,
                             int* __restrict__ srcC, int* __restrict__ srcL, int E) {
    int e = blockIdx.x * 256 + threadIdx.x;
    if (e >= E) return;
    int s = esrc[e], d = edst[e];
    int pC = atomicAdd(&curC[d], 1);
    srcC[pC] = s;
    int pL = atomicAdd(&curL[s], 1);
    srcL[pL] = d;
}

// ---------------- segment sum over fp16 rows ----------------------------------
__global__ void segsum_kernel(const uint32_t* __restrict__ rows,
                              const int* __restrict__ rowptr,
                              const int* __restrict__ srcidx,
                              uint32_t* __restrict__ out, int M) {
    int seg = blockIdx.x * 8 + (threadIdx.x >> 5);
    if (seg >= M) return;
    const int lane = threadIdx.x & 31;
    const int beg = rowptr[seg], end = rowptr[seg + 1];
    float4 v = make_float4(0.f, 0.f, 0.f, 0.f);
    for (int j = beg; j < end; ++j) {
        int s = srcidx[j];
        uint2 u = *(const uint2*)(rows + (size_t)s * 64 + lane * 2);
        float2 a = __half22float2(*(__half2*)&u.x);
        float2 b = __half22float2(*(__half2*)&u.y);
        v.x += a.x; v.y += a.y; v.z += b.x; v.w += b.y;
    }
    *(uint2*)(out + (size_t)seg * 64 + lane * 2) =
        make_uint2(cvt2h(v.x, v.y), cvt2h(v.z, v.w));
}

// ---------------- small kernels ----------------------------------------------
__global__ void init_kernel(const float* __restrict__ lw, const float* __restrict__ lb,
                            const float* __restrict__ cw, const float* __restrict__ cb,
                            float* __restrict__ h,
                            uint32_t* __restrict__ lh, uint32_t* __restrict__ chh) {
    int tid = threadIdx.x;           // 0..63
    size_t row = blockIdx.x;
    int d0 = tid * 2;
    float v0, v1;
    if (row < V2_) { v0 = lw[d0] + lb[d0]; v1 = lw[d0 + 1] + lb[d0 + 1]; }
    else           { v0 = cw[d0] + cb[d0]; v1 = cw[d0 + 1] + cb[d0 + 1]; }
    h[row * D_ + d0] = v0;
    h[row * D_ + d0 + 1] = v1;
    uint32_t pv = cvt2h(v0, v1);
    if (row < V2_) lh[row * 64 + tid] = pv;
    else           chh[(row - V2_) * 64 + tid] = pv;
}

__global__ void cvt_pairs(const float2* __restrict__ src,
                          uint32_t* __restrict__ dst, size_t n) {
    size_t i = (size_t)blockIdx.x * blockDim.x + threadIdx.x;
    if (i >= n) return;
    float2 v = src[i];
    dst[i] = cvt2h(v.x, v.y);
}

// gate-interleaved row permutation: new pr -> old row
__global__ void cvt_perm(const float2* __restrict__ src,
                         uint32_t* __restrict__ dst, int ld32) {
    int i = blockIdx.x * 256 + threadIdx.x;
    int n = 512 * ld32;
    if (i >= n) return;
    int pr = i / ld32, cc = i % ld32;
    int nt = pr >> 7, w = pr & 127;
    int wb = w >> 5, q = w & 31;
    int old = (q >> 3) * 128 + nt * 32 + wb * 8 + (q & 7);
    float2 v = src[(size_t)old * ld32 + cc];
    dst[i] = cvt2h(v.x, v.y);
}

__global__ void perm_bias(const float* __restrict__ b0, const float* __restrict__ b1,
                          float* __restrict__ out) {
    int pr = blockIdx.x * 256 + threadIdx.x;
    if (pr >= 512) return;
    int nt = pr >> 7, w = pr & 127;
    int wb = w >> 5, q = w & 31;
    int old = (q >> 3) * 128 + nt * 32 + wb * 8 + (q & 7);
    out[pr] = b0[old] + b1[old];
}

__global__ void zero_kernel(float4* __restrict__ p, size_t n4) {
    size_t i = (size_t)blockIdx.x * blockDim.x + threadIdx.x;
    if (i < n4) p[i] = make_float4(0.f, 0.f, 0.f, 0.f);
}

__global__ void copy_kernel(const float4* __restrict__ src, float4* __restrict__ dst, size_t n4) {
    size_t i = (size_t)blockIdx.x * blockDim.x + threadIdx.x;
    if (i < n4) dst[i] = src[i];
}

// ---------------- host -------------------------------------------------------
extern "C" void kernel_launch(void* const* d_in, const int* in_sizes, int n_in,
                              void* d_out, int out_size) {
    const float* L_init_w = (const float*)d_in[0];
    const float* L_init_b = (const float*)d_in[1];
    const float* C_init_w = (const float*)d_in[2];
    const float* C_init_b = (const float*)d_in[3];
    const float* Lmsg_w   = (const float*)d_in[4];
    const float* Lmsg_b   = (const float*)d_in[5];
    const float* Cmsg_w   = (const float*)d_in[6];
    const float* Cmsg_b   = (const float*)d_in[7];
    const float* Cu_wih   = (const float*)d_in[8];
    const float* Cu_whh   = (const float*)d_in[9];
    const float* Cu_bih   = (const float*)d_in[10];
    const float* Cu_bhh   = (const float*)d_in[11];
    const float* Lu_wih   = (const float*)d_in[12];
    const float* Lu_whh   = (const float*)d_in[13];
    const float* Lu_bih   = (const float*)d_in[14];
    const float* Lu_bhh   = (const float*)d_in[15];
    const int*   esrc     = (const int*)d_in[16];
    const int*   edst     = (const int*)d_in[17];
    const int E = in_sizes[16];

    static int smem_set = 0;
    if (!smem_set) {
        cudaFuncSetAttribute(gates3_kernel, cudaFuncAttributeMaxDynamicSharedMemorySize, SMEM_G3);
        cudaFuncSetAttribute(mlp3_kernel, cudaFuncAttributeMaxDynamicSharedMemorySize, SMEM_MLP);
        cudaFuncSetAttribute(gates2_kernel, cudaFuncAttributeMaxDynamicSharedMemorySize, SMEM_G2);
        smem_set = 1;
    }

    float *h, *c, *pbC, *pbL;
    uint32_t *t0, *chh, *lhA, *lhB, *mm, *wh;
    int *cntC, *cntL, *curC, *curL, *srcC, *srcL;
    cudaGetSymbolAddress((void**)&h,     g_h);
    cudaGetSymbolAddress((void**)&c,     g_c);
    cudaGetSymbolAddress((void**)&t0,    g_t0);
    cudaGetSymbolAddress((void**)&chh,   g_chh);
    cudaGetSymbolAddress((void**)&lhA,   g_lhA);
    cudaGetSymbolAddress((void**)&lhB,   g_lhB);
    cudaGetSymbolAddress((void**)&mm,    g_mm);
    cudaGetSymbolAddress((void**)&wh,    g_wh);
    cudaGetSymbolAddress((void**)&pbC,   g_pbC);
    cudaGetSymbolAddress((void**)&pbL,   g_pbL);
    cudaGetSymbolAddress((void**)&cntC,  g_cntC);
    cudaGetSymbolAddress((void**)&cntL,  g_cntL);
    cudaGetSymbolAddress((void**)&curC,  g_curC);
    cudaGetSymbolAddress((void**)&curL,  g_curL);
    cudaGetSymbolAddress((void**)&srcC,  g_srcC);
    cudaGetSymbolAddress((void**)&srcL,  g_srcL);

    // ---- pre-convert weights (gate matrices row-permuted) ----
    cvt_pairs<<<(24576 + 255) / 256, 256>>>((const float2*)Lmsg_w, wh + WO_LMSG, 24576);
    cvt_pairs<<<(24576 + 255) / 256, 256>>>((const float2*)Cmsg_w, wh + WO_CMSG, 24576);
    cvt_perm<<<128, 256>>>((const float2*)Cu_wih, wh + WO_CWIH, 64);
    cvt_perm<<<128, 256>>>((const float2*)Cu_whh, wh + WO_CWHH, 64);
    cvt_perm<<<256, 256>>>((const float2*)Lu_wih, wh + WO_LWIH, 128);
    cvt_perm<<<128, 256>>>((const float2*)Lu_whh, wh + WO_LWHH, 64);
    perm_bias<<<2, 256>>>(Cu_bih, Cu_bhh, pbC);
    perm_bias<<<2, 256>>>(Lu_bih, Lu_bhh, pbL);

    // ---- build CSR ----
    zero_int_kernel<<<(NCL + 256) / 256, 256>>>(cntC, NCL + 1);
    zero_int_kernel<<<(V2_ + 256) / 256, 256>>>(cntL, V2_ + 1);
    hist_kernel<<<(E + 255) / 256, 256>>>(esrc, edst, cntC, cntL, E);
    scan_kernel<<<1, 1024>>>(cntC, curC, NCL);
    scan_kernel<<<1, 1024>>>(cntL, curL, V2_);
    place_kernel<<<(E + 255) / 256, 256>>>(esrc, edst, curC, curL, srcC, srcL, E);

    init_kernel<<<NTOTAL, 64>>>(L_init_w, L_init_b, C_init_w, C_init_b, h, lhA, chh);
    zero_kernel<<<((size_t)NTOTAL * 32 + 255) / 256, 256>>>((float4*)c, (size_t)NTOTAL * 32);

    const int gv = (V2_ + 127) >> 7;    // 782
    const int gc = (NCL + 127) >> 7;    // 1563

    uint32_t* lh_cur = lhA;
    uint32_t* lh_nxt = lhB;

    for (int r = 0; r < NROUNDS; ++r) {
        // ---- L-MLP fused -> t0 (fp16) ----
        mlp3_kernel<<<gv, 512, SMEM_MLP>>>(lh_cur, wh + WO_LMSG, Lmsg_b, t0, V2_);
        segsum_kernel<<<(NCL + 7) / 8, 256>>>(t0, cntC, srcC, mm, NCL);

        // ---- clause gates + fused LSTM (in-place clause hh update) ----
        gates2_kernel<<<gc, 512, SMEM_G2>>>(
            mm, chh, wh + WO_CWIH, wh + WO_CWHH, pbC,
            c + (size_t)V2_ * D_, h + (size_t)V2_ * D_, chh, NCL);

        // ---- C-MLP fused -> t0 (fp16) ----
        mlp3_kernel<<<gc, 512, SMEM_MLP>>>(chh, wh + WO_CMSG, Cmsg_b, t0, NCL);
        segsum_kernel<<<(V2_ + 7) / 8, 256>>>(t0, cntL, srcL, mm, V2_);

        // ---- literal gates (3-term, A resident) + fused LSTM ----
        gates3_kernel<<<gv, 512, SMEM_G3>>>(
            mm, lh_cur, wh + WO_LWIH, wh + WO_LWHH, pbL,
            c, h, lh_nxt, V2_);

        uint32_t* tmp = lh_cur; lh_cur = lh_nxt; lh_nxt = tmp;
    }

    copy_kernel<<<((size_t)NTOTAL * 32 + 255) / 256, 256>>>(
        (const float4*)h, (float4*)d_out, (size_t)NTOTAL * 32);
}